// round 1
// baseline (speedup 1.0000x reference)
#include <cuda_runtime.h>

#define BB 4
#define CC 256
#define TT 4096
#define CQ 32

// Scratch (allocation-free: __device__ globals)
__device__ float g_q[(size_t)BB * CQ * TT];                 // [B, Cq, T]
__device__ float g_k[(size_t)BB * CQ * TT];                 // [B, Cq, T]
__device__ float g_v[(size_t)BB * CC * TT];                 // [B, C, T]
__device__ float g_attn[(size_t)BB * TT * TT];              // [B, T, T] (256 MB)

// ---------------------------------------------------------------------------
// Kernel 1: q/k/v projections. One block = one (b, 32-t tile). 320 threads,
// one output row each (32 q + 32 k + 256 v). x tile cached in smem.
// ---------------------------------------------------------------------------
__global__ __launch_bounds__(320) void proj_kernel(
    const float* __restrict__ x,
    const float* __restrict__ Wq, const float* __restrict__ bq,
    const float* __restrict__ Wk, const float* __restrict__ bk,
    const float* __restrict__ Wv, const float* __restrict__ bv)
{
    __shared__ float xs[CC * 32];                           // [c][t], t fastest
    int b  = blockIdx.x >> 7;                               // T/32 = 128 tiles
    int t0 = (blockIdx.x & 127) << 5;
    const float* xb = x + ((size_t)b * CC) * TT + t0;

    for (int i = threadIdx.x; i < CC * 32; i += 320) {
        int c = i >> 5, t = i & 31;
        xs[i] = xb[(size_t)c * TT + t];
    }
    __syncthreads();

    int o = threadIdx.x;
    const float* Wrow;
    float bias;
    float* outp;
    if (o < CQ) {
        Wrow = Wq + o * CC; bias = bq[o];
        outp = g_q + ((size_t)(b * CQ + o)) * TT + t0;
    } else if (o < 2 * CQ) {
        int r = o - CQ;
        Wrow = Wk + r * CC; bias = bk[r];
        outp = g_k + ((size_t)(b * CQ + r)) * TT + t0;
    } else {
        int r = o - 2 * CQ;
        Wrow = Wv + r * CC; bias = bv[r];
        outp = g_v + ((size_t)(b * CC + r)) * TT + t0;
    }

    float acc[32];
#pragma unroll
    for (int t = 0; t < 32; t++) acc[t] = bias;

    const float4* w4 = (const float4*)Wrow;
#pragma unroll 4
    for (int c4 = 0; c4 < CC / 4; c4++) {
        float4 w = w4[c4];
        float wc[4] = {w.x, w.y, w.z, w.w};
#pragma unroll
        for (int u = 0; u < 4; u++) {
            const float4* xr = (const float4*)(xs + (c4 * 4 + u) * 32);
#pragma unroll
            for (int t4 = 0; t4 < 8; t4++) {
                float4 xv = xr[t4];
                acc[t4 * 4 + 0] += wc[u] * xv.x;
                acc[t4 * 4 + 1] += wc[u] * xv.y;
                acc[t4 * 4 + 2] += wc[u] * xv.z;
                acc[t4 * 4 + 3] += wc[u] * xv.w;
            }
        }
    }
#pragma unroll
    for (int t = 0; t < 32; t++) outp[t] = acc[t];
}

// ---------------------------------------------------------------------------
// Kernel 2: raw scores S[b,t,s] = sum_d q[b,d,t] * k[b,d,s].
// One block = (b, 64-t tile), loops over s in chunks of 128.
// Each thread computes 2 t-rows x 16 s.
// ---------------------------------------------------------------------------
__global__ __launch_bounds__(256) void scores_kernel()
{
    __shared__ float qs[CQ * 64];                           // [d][t]
    __shared__ float ks[CQ * 128];                          // [d][s]
    int b     = blockIdx.x >> 6;                            // T/64 = 64 tiles
    int tBase = (blockIdx.x & 63) << 6;

    for (int i = threadIdx.x; i < CQ * 64; i += 256) {
        int d = i >> 6, t = i & 63;
        qs[i] = g_q[((size_t)(b * CQ + d)) * TT + tBase + t];
    }

    int sg = threadIdx.x & 7, tp = threadIdx.x >> 3;
    int t0 = tp * 2, s0 = sg * 16;

    for (int sBase = 0; sBase < TT; sBase += 128) {
        __syncthreads();                                    // qs ready / ks reuse
        for (int i = threadIdx.x; i < CQ * 128; i += 256) {
            int d = i >> 7, s = i & 127;
            ks[i] = g_k[((size_t)(b * CQ + d)) * TT + sBase + s];
        }
        __syncthreads();

        float acc0[16], acc1[16];
#pragma unroll
        for (int j = 0; j < 16; j++) { acc0[j] = 0.f; acc1[j] = 0.f; }

#pragma unroll
        for (int d = 0; d < CQ; d++) {
            float qa = qs[d * 64 + t0];
            float qb = qs[d * 64 + t0 + 1];
            const float4* kr = (const float4*)(ks + d * 128 + s0);
#pragma unroll
            for (int j4 = 0; j4 < 4; j4++) {
                float4 kv = kr[j4];
                acc0[j4 * 4 + 0] += qa * kv.x; acc0[j4 * 4 + 1] += qa * kv.y;
                acc0[j4 * 4 + 2] += qa * kv.z; acc0[j4 * 4 + 3] += qa * kv.w;
                acc1[j4 * 4 + 0] += qb * kv.x; acc1[j4 * 4 + 1] += qb * kv.y;
                acc1[j4 * 4 + 2] += qb * kv.z; acc1[j4 * 4 + 3] += qb * kv.w;
            }
        }

        float* ar = g_attn + ((size_t)(b * TT + tBase + t0)) * TT + sBase + s0;
        float4* a0p = (float4*)ar;
        float4* a1p = (float4*)(ar + TT);
#pragma unroll
        for (int j4 = 0; j4 < 4; j4++) {
            a0p[j4] = make_float4(acc0[j4 * 4 + 0], acc0[j4 * 4 + 1],
                                  acc0[j4 * 4 + 2], acc0[j4 * 4 + 3]);
            a1p[j4] = make_float4(acc1[j4 * 4 + 0], acc1[j4 * 4 + 1],
                                  acc1[j4 * 4 + 2], acc1[j4 * 4 + 3]);
        }
    }
}

// ---------------------------------------------------------------------------
// Kernel 3: row-wise softmax in place over g_attn. One block per (b,t) row.
// ---------------------------------------------------------------------------
__global__ __launch_bounds__(256) void softmax_kernel()
{
    __shared__ float row[TT];
    __shared__ float red[8];
    float* gr = g_attn + (size_t)blockIdx.x * TT;
    float4* gr4  = (float4*)gr;
    float4* row4 = (float4*)row;
    int tid  = threadIdx.x;
    int lane = tid & 31, warp = tid >> 5;

    float lmax = -1e30f;
    for (int i = tid; i < TT / 4; i += 256) {
        float4 v = gr4[i];
        row4[i] = v;
        lmax = fmaxf(lmax, fmaxf(fmaxf(v.x, v.y), fmaxf(v.z, v.w)));
    }
#pragma unroll
    for (int off = 16; off; off >>= 1)
        lmax = fmaxf(lmax, __shfl_xor_sync(0xffffffffu, lmax, off));
    if (lane == 0) red[warp] = lmax;
    __syncthreads();
    if (tid < 32) {
        float v = (tid < 8) ? red[tid] : -1e30f;
#pragma unroll
        for (int off = 4; off; off >>= 1)
            v = fmaxf(v, __shfl_xor_sync(0xffffffffu, v, off));
        if (tid == 0) red[0] = v;
    }
    __syncthreads();
    float m = red[0];

    float lsum = 0.f;
    for (int i = tid; i < TT / 4; i += 256) {
        float4 v = row4[i];
        v.x = expf(v.x - m); v.y = expf(v.y - m);
        v.z = expf(v.z - m); v.w = expf(v.w - m);
        row4[i] = v;
        lsum += v.x + v.y + v.z + v.w;
    }
    __syncthreads();                                        // everyone has read red[0]
#pragma unroll
    for (int off = 16; off; off >>= 1)
        lsum += __shfl_xor_sync(0xffffffffu, lsum, off);
    if (lane == 0) red[warp] = lsum;
    __syncthreads();
    if (tid < 32) {
        float v = (tid < 8) ? red[tid] : 0.f;
#pragma unroll
        for (int off = 4; off; off >>= 1)
            v += __shfl_xor_sync(0xffffffffu, v, off);
        if (tid == 0) red[0] = v;
    }
    __syncthreads();
    float inv = 1.0f / red[0];

    for (int i = tid; i < TT / 4; i += 256) {
        float4 v = row4[i];
        v.x *= inv; v.y *= inv; v.z *= inv; v.w *= inv;
        gr4[i] = v;
    }
}

// ---------------------------------------------------------------------------
// Kernel 4: out[b,c,t] = sum_s v[b,c,s] * attn[b,t,s] + x[b,c,t].
// Batched GEMM, both operands s-contiguous. 128x128x32 tiles, 8x8 per thread.
// ---------------------------------------------------------------------------
__global__ __launch_bounds__(256) void pv_kernel(
    const float* __restrict__ x, float* __restrict__ out)
{
    __shared__ float Vs[32][132];                           // [s][c], padded
    __shared__ float As[32][132];                           // [s][t], padded
    int b     = blockIdx.z;
    int cBase = blockIdx.y << 7;
    int tBase = blockIdx.x << 7;
    int tid   = threadIdx.x;
    int ty = tid >> 4, tx = tid & 15;
    int c0 = ty << 3, t0 = tx << 3;

    float acc[8][8];
#pragma unroll
    for (int i = 0; i < 8; i++)
#pragma unroll
        for (int j = 0; j < 8; j++) acc[i][j] = 0.f;

    const float* vbase = g_v    + ((size_t)(b * CC + cBase)) * TT;
    const float* abase = g_attn + ((size_t)(b * TT + tBase)) * TT;

    for (int sBase = 0; sBase < TT; sBase += 32) {
        for (int i = tid; i < 128 * 32; i += 256) {
            int r = i >> 5, s = i & 31;
            Vs[s][r] = vbase[(size_t)r * TT + sBase + s];
            As[s][r] = abase[(size_t)r * TT + sBase + s];
        }
        __syncthreads();

#pragma unroll 4
        for (int s = 0; s < 32; s++) {
            float4 v0 = *(const float4*)&Vs[s][c0];
            float4 v1 = *(const float4*)&Vs[s][c0 + 4];
            float4 a0 = *(const float4*)&As[s][t0];
            float4 a1 = *(const float4*)&As[s][t0 + 4];
            float vv[8] = {v0.x, v0.y, v0.z, v0.w, v1.x, v1.y, v1.z, v1.w};
            float aa[8] = {a0.x, a0.y, a0.z, a0.w, a1.x, a1.y, a1.z, a1.w};
#pragma unroll
            for (int i = 0; i < 8; i++)
#pragma unroll
                for (int j = 0; j < 8; j++)
                    acc[i][j] += vv[i] * aa[j];
        }
        __syncthreads();
    }

#pragma unroll
    for (int i = 0; i < 8; i++) {
        size_t rowoff = ((size_t)(b * CC + cBase + c0 + i)) * TT + tBase + t0;
        const float4* xr = (const float4*)(x + rowoff);
        float4* orow = (float4*)(out + rowoff);
        float4 x0 = xr[0], x1 = xr[1];
        orow[0] = make_float4(acc[i][0] + x0.x, acc[i][1] + x0.y,
                              acc[i][2] + x0.z, acc[i][3] + x0.w);
        orow[1] = make_float4(acc[i][4] + x1.x, acc[i][5] + x1.y,
                              acc[i][6] + x1.z, acc[i][7] + x1.w);
    }
}

// ---------------------------------------------------------------------------
extern "C" void kernel_launch(void* const* d_in, const int* in_sizes, int n_in,
                              void* d_out, int out_size)
{
    const float* x  = (const float*)d_in[0];
    const float* Wq = (const float*)d_in[1];
    const float* bq = (const float*)d_in[2];
    const float* Wk = (const float*)d_in[3];
    const float* bk = (const float*)d_in[4];
    const float* Wv = (const float*)d_in[5];
    const float* bv = (const float*)d_in[6];
    float* out = (float*)d_out;

    proj_kernel<<<BB * (TT / 32), 320>>>(x, Wq, bq, Wk, bk, Wv, bv);
    scores_kernel<<<BB * (TT / 64), 256>>>();
    softmax_kernel<<<BB * TT, 256>>>();
    dim3 g4(TT / 128, CC / 128, BB);
    pv_kernel<<<g4, 256>>>(x, out);
}

// round 3
// speedup vs baseline: 2.6260x; 2.6260x over previous
#include <cuda_runtime.h>
#include <cstdint>

#define BB 4
#define CC 256
#define TT 4096
#define CQ 32

// ---------------------------------------------------------------------------
// Scratch (allocation-free: __device__ globals)
// ---------------------------------------------------------------------------
__device__ float g_qs[(size_t)BB * TT * 64];   // [B*T][64]: 0-31 q_hi(tf32), 32-63 q_lo
__device__ float g_ks[(size_t)BB * TT * 64];   // [B*T][64]: k_hi | k_lo
__device__ float g_v[(size_t)BB * CC * TT];    // [B, C, T], tf32-rounded
__device__ float g_attn[(size_t)BB * TT * TT]; // [B, T, T] (256 MB)

// ---------------------------------------------------------------------------
// Helpers (target-agnostic PTX only: mma.sync + cp.async, sm_80+ baseline)
// ---------------------------------------------------------------------------
__device__ __forceinline__ uint32_t smem_to_u32(const void* p) {
    uint32_t a;
    asm("{ .reg .u64 t; cvta.to.shared.u64 t, %1; cvt.u32.u64 %0, t; }" : "=r"(a) : "l"(p));
    return a;
}
__device__ __forceinline__ float tf32_rna(float x) {
    float r;
    asm("cvt.rna.tf32.f32 %0, %1;" : "=f"(r) : "f"(x));
    return r;
}
__device__ __forceinline__ void mma_tf32(float* c, const uint32_t* a, const uint32_t* b) {
    asm volatile(
        "mma.sync.aligned.m16n8k8.row.col.f32.tf32.tf32.f32 "
        "{%0,%1,%2,%3}, {%4,%5,%6,%7}, {%8,%9}, {%0,%1,%2,%3};"
        : "+f"(c[0]), "+f"(c[1]), "+f"(c[2]), "+f"(c[3])
        : "r"(a[0]), "r"(a[1]), "r"(a[2]), "r"(a[3]), "r"(b[0]), "r"(b[1]));
}
__device__ __forceinline__ void cp_async16(uint32_t dst, const void* src) {
    asm volatile("cp.async.cg.shared.global [%0], [%1], 16;" :: "r"(dst), "l"(src));
}
#define CP_COMMIT() asm volatile("cp.async.commit_group;" ::: "memory")
#define CP_WAIT(n)  asm volatile("cp.async.wait_group %0;" :: "n"(n) : "memory")

// ---------------------------------------------------------------------------
// Kernel 1: q/k/v projections. Writes tf32-split q,k (transposed) + tf32 v.
// ---------------------------------------------------------------------------
__global__ __launch_bounds__(320) void proj_kernel(
    const float* __restrict__ x,
    const float* __restrict__ Wq, const float* __restrict__ bq,
    const float* __restrict__ Wk, const float* __restrict__ bk,
    const float* __restrict__ Wv, const float* __restrict__ bv)
{
    __shared__ float xs[CC * 32];                           // [c][t]
    int b  = blockIdx.x >> 7;
    int t0 = (blockIdx.x & 127) << 5;
    const float* xb = x + ((size_t)b * CC) * TT + t0;

    for (int i = threadIdx.x; i < CC * 32; i += 320) {
        int c = i >> 5, t = i & 31;
        xs[i] = xb[(size_t)c * TT + t];
    }
    __syncthreads();

    int o = threadIdx.x;
    const float* Wrow;
    float bias;
    if (o < CQ)          { Wrow = Wq + o * CC;            bias = bq[o]; }
    else if (o < 2 * CQ) { Wrow = Wk + (o - CQ) * CC;     bias = bk[o - CQ]; }
    else                 { Wrow = Wv + (o - 2 * CQ) * CC; bias = bv[o - 2 * CQ]; }

    float acc[32];
#pragma unroll
    for (int t = 0; t < 32; t++) acc[t] = bias;

    const float4* w4 = (const float4*)Wrow;
#pragma unroll 4
    for (int c4 = 0; c4 < CC / 4; c4++) {
        float4 w = w4[c4];
        float wc[4] = {w.x, w.y, w.z, w.w};
#pragma unroll
        for (int u = 0; u < 4; u++) {
            const float4* xr = (const float4*)(xs + (c4 * 4 + u) * 32);
#pragma unroll
            for (int t4 = 0; t4 < 8; t4++) {
                float4 xv = xr[t4];
                acc[t4 * 4 + 0] += wc[u] * xv.x;
                acc[t4 * 4 + 1] += wc[u] * xv.y;
                acc[t4 * 4 + 2] += wc[u] * xv.z;
                acc[t4 * 4 + 3] += wc[u] * xv.w;
            }
        }
    }

    if (o < 2 * CQ) {
        float* base = (o < CQ) ? g_qs : g_ks;
        int r = o & 31;
        size_t rowb = (size_t)b * TT + t0;
#pragma unroll
        for (int t = 0; t < 32; t++) {
            float v  = acc[t];
            float hi = tf32_rna(v);
            base[(rowb + t) * 64 + r]      = hi;
            base[(rowb + t) * 64 + 32 + r] = v - hi;
        }
    } else {
        float* outp = g_v + ((size_t)(b * CC + (o - 2 * CQ))) * TT + t0;
#pragma unroll
        for (int t = 0; t < 32; t++) outp[t] = tf32_rna(acc[t]);
    }
}

// ---------------------------------------------------------------------------
// Kernel 2: scores via mma.sync tf32, exact 2-term split (4 K-region passes).
// CTA: 128 t x 128 s, 8 warps (2x4), warp tile 64x32.
// ---------------------------------------------------------------------------
static constexpr int SC_STRIDE = 68;                        // floats per smem row
static constexpr int SMEM_SC = 2 * 128 * SC_STRIDE * 4;     // 69632 B

__global__ __launch_bounds__(256, 1) void scores_kernel()
{
    extern __shared__ float sm[];
    float* Qs = sm;
    float* Ks = sm + 128 * SC_STRIDE;
    int tid = threadIdx.x;
    int b = blockIdx.z, tBase = blockIdx.y << 7, sBase = blockIdx.x << 7;

    const float* qsrc = g_qs + ((size_t)b * TT + tBase) * 64;
    const float* ksrc = g_ks + ((size_t)b * TT + sBase) * 64;
    for (int i = tid; i < 2048; i += 256) {                 // 128 rows x 16 float4
        int r = i >> 4, c4 = i & 15;
        *(float4*)(Qs + r * SC_STRIDE + c4 * 4) = *(const float4*)(qsrc + r * 64 + c4 * 4);
        *(float4*)(Ks + r * SC_STRIDE + c4 * 4) = *(const float4*)(ksrc + r * 64 + c4 * 4);
    }
    __syncthreads();

    int lane = tid & 31, wid = tid >> 5, g = lane >> 2, t4 = lane & 3;
    int m0 = (wid >> 2) * 64, n0 = (wid & 3) * 32;

    float acc[4][4][4] = {};
    const uint32_t* Q32 = (const uint32_t*)Qs;
    const uint32_t* K32 = (const uint32_t*)Ks;

    const int amap[4] = {0, 0, 32, 32};                     // (qh,kh)(qh,kl)(ql,kh)(ql,kl)
    const int bmap[4] = {0, 32, 0, 32};
#pragma unroll
    for (int p = 0; p < 4; p++) {
#pragma unroll
        for (int kk = 0; kk < 4; kk++) {
            int ka = amap[p] + kk * 8 + t4;
            int kb = bmap[p] + kk * 8 + t4;
            uint32_t a[4][4], bf[4][2];
#pragma unroll
            for (int mt = 0; mt < 4; mt++) {
                int r = m0 + mt * 16 + g;
                a[mt][0] = Q32[r * SC_STRIDE + ka];
                a[mt][1] = Q32[(r + 8) * SC_STRIDE + ka];
                a[mt][2] = Q32[r * SC_STRIDE + ka + 4];
                a[mt][3] = Q32[(r + 8) * SC_STRIDE + ka + 4];
            }
#pragma unroll
            for (int nt = 0; nt < 4; nt++) {
                int s = n0 + nt * 8 + g;
                bf[nt][0] = K32[s * SC_STRIDE + kb];
                bf[nt][1] = K32[s * SC_STRIDE + kb + 4];
            }
#pragma unroll
            for (int mt = 0; mt < 4; mt++)
#pragma unroll
                for (int nt = 0; nt < 4; nt++)
                    mma_tf32(acc[mt][nt], a[mt], bf[nt]);
        }
    }

    float* dst = g_attn + ((size_t)b * TT + tBase) * TT + sBase;
#pragma unroll
    for (int mt = 0; mt < 4; mt++)
#pragma unroll
        for (int nt = 0; nt < 4; nt++) {
            int row = m0 + mt * 16 + g, col = n0 + nt * 8 + 2 * t4;
            *(float2*)(dst + (size_t)row * TT + col) =
                make_float2(acc[mt][nt][0], acc[mt][nt][1]);
            *(float2*)(dst + (size_t)(row + 8) * TT + col) =
                make_float2(acc[mt][nt][2], acc[mt][nt][3]);
        }
}

// ---------------------------------------------------------------------------
// Kernel 3: row-wise softmax in place; stores tf32-rounded weights.
// ---------------------------------------------------------------------------
__global__ __launch_bounds__(256) void softmax_kernel()
{
    __shared__ float row[TT];
    __shared__ float red[8];
    float* gr = g_attn + (size_t)blockIdx.x * TT;
    float4* gr4  = (float4*)gr;
    float4* row4 = (float4*)row;
    int tid = threadIdx.x, lane = tid & 31, warp = tid >> 5;

    float lmax = -1e30f;
    for (int i = tid; i < TT / 4; i += 256) {
        float4 v = gr4[i];
        row4[i] = v;
        lmax = fmaxf(lmax, fmaxf(fmaxf(v.x, v.y), fmaxf(v.z, v.w)));
    }
#pragma unroll
    for (int off = 16; off; off >>= 1)
        lmax = fmaxf(lmax, __shfl_xor_sync(0xffffffffu, lmax, off));
    if (lane == 0) red[warp] = lmax;
    __syncthreads();
    if (tid < 32) {
        float v = (tid < 8) ? red[tid] : -1e30f;
#pragma unroll
        for (int off = 4; off; off >>= 1)
            v = fmaxf(v, __shfl_xor_sync(0xffffffffu, v, off));
        if (tid == 0) red[0] = v;
    }
    __syncthreads();
    float m = red[0];

    float lsum = 0.f;
    for (int i = tid; i < TT / 4; i += 256) {
        float4 v = row4[i];
        v.x = __expf(v.x - m); v.y = __expf(v.y - m);
        v.z = __expf(v.z - m); v.w = __expf(v.w - m);
        row4[i] = v;
        lsum += v.x + v.y + v.z + v.w;
    }
    __syncthreads();
#pragma unroll
    for (int off = 16; off; off >>= 1)
        lsum += __shfl_xor_sync(0xffffffffu, lsum, off);
    if (lane == 0) red[warp] = lsum;
    __syncthreads();
    if (tid < 32) {
        float v = (tid < 8) ? red[tid] : 0.f;
#pragma unroll
        for (int off = 4; off; off >>= 1)
            v += __shfl_xor_sync(0xffffffffu, v, off);
        if (tid == 0) red[0] = v;
    }
    __syncthreads();
    float inv = 1.0f / red[0];

    for (int i = tid; i < TT / 4; i += 256) {
        float4 v = row4[i];
        v.x = tf32_rna(v.x * inv); v.y = tf32_rna(v.y * inv);
        v.z = tf32_rna(v.z * inv); v.w = tf32_rna(v.w * inv);
        gr4[i] = v;
    }
}

// ---------------------------------------------------------------------------
// Kernel 4: out = V @ attn^T + x via mma.sync tf32. CTA 128c x 128t, K=4096.
// 2-stage cp.async double buffering, 32-wide K chunks.
// ---------------------------------------------------------------------------
static constexpr int PV_STRIDE = 36;                        // floats per smem row
static constexpr int PV_BUF = 128 * PV_STRIDE;              // floats per panel
static constexpr int SMEM_PV = 4 * PV_BUF * 4;              // 73728 B

__global__ __launch_bounds__(256, 1) void pv_kernel(
    const float* __restrict__ x, float* __restrict__ out)
{
    extern __shared__ float sm[];
    uint32_t sb = smem_to_u32(sm);
    int tid = threadIdx.x;
    int b = blockIdx.z, cBase = blockIdx.y << 7, tBase = blockIdx.x << 7;

    const float* va = g_v    + ((size_t)(b * CC + cBase)) * TT;
    const float* aa = g_attn + ((size_t)b * TT + tBase) * TT;

    int lane = tid & 31, wid = tid >> 5, g = lane >> 2, t4 = lane & 3;
    int m0 = (wid >> 2) * 64, n0 = (wid & 3) * 32;

    // thread's fixed load slots: 4 rows x (A,B)
    int lr = tid >> 3, lc4 = tid & 7;

    float acc[4][4][4] = {};

    // prologue: chunk 0 -> buf 0
    {
        uint32_t Ad = sb, Bd = sb + PV_BUF * 4;
#pragma unroll
        for (int q = 0; q < 4; q++) {
            int r = lr + q * 32;
            uint32_t off = r * (PV_STRIDE * 4) + lc4 * 16;
            cp_async16(Ad + off, va + (size_t)r * TT + lc4 * 4);
            cp_async16(Bd + off, aa + (size_t)r * TT + lc4 * 4);
        }
        CP_COMMIT();
    }

    for (int ch = 0; ch < TT / 32; ch++) {
        int buf = ch & 1;
        if (ch + 1 < TT / 32) {
            uint32_t Ad = sb + (buf ^ 1) * 2 * PV_BUF * 4;
            uint32_t Bd = Ad + PV_BUF * 4;
            const float* va2 = va + (ch + 1) * 32;
            const float* aa2 = aa + (ch + 1) * 32;
#pragma unroll
            for (int q = 0; q < 4; q++) {
                int r = lr + q * 32;
                uint32_t off = r * (PV_STRIDE * 4) + lc4 * 16;
                cp_async16(Ad + off, va2 + (size_t)r * TT + lc4 * 4);
                cp_async16(Bd + off, aa2 + (size_t)r * TT + lc4 * 4);
            }
            CP_COMMIT();
            CP_WAIT(1);
        } else {
            CP_WAIT(0);
        }
        __syncthreads();

        const uint32_t* As = (const uint32_t*)(sm + buf * 2 * PV_BUF);
        const uint32_t* Bs = (const uint32_t*)(sm + (buf * 2 + 1) * PV_BUF);
#pragma unroll
        for (int kk = 0; kk < 4; kk++) {
            int kb = kk * 8 + t4;
            uint32_t a[4][4], bf[4][2];
#pragma unroll
            for (int mt = 0; mt < 4; mt++) {
                int r = m0 + mt * 16 + g;
                a[mt][0] = As[r * PV_STRIDE + kb];
                a[mt][1] = As[(r + 8) * PV_STRIDE + kb];
                a[mt][2] = As[r * PV_STRIDE + kb + 4];
                a[mt][3] = As[(r + 8) * PV_STRIDE + kb + 4];
            }
#pragma unroll
            for (int nt = 0; nt < 4; nt++) {
                int s = n0 + nt * 8 + g;
                bf[nt][0] = Bs[s * PV_STRIDE + kb];
                bf[nt][1] = Bs[s * PV_STRIDE + kb + 4];
            }
#pragma unroll
            for (int mt = 0; mt < 4; mt++)
#pragma unroll
                for (int nt = 0; nt < 4; nt++)
                    mma_tf32(acc[mt][nt], a[mt], bf[nt]);
        }
        __syncthreads();
    }

    // epilogue: out = acc + x
#pragma unroll
    for (int mt = 0; mt < 4; mt++)
#pragma unroll
        for (int nt = 0; nt < 4; nt++) {
            int crow = cBase + m0 + mt * 16 + g;
            int tcol = tBase + n0 + nt * 8 + 2 * t4;
            size_t o0 = ((size_t)(b * CC + crow)) * TT + tcol;
            size_t o1 = ((size_t)(b * CC + crow + 8)) * TT + tcol;
            float2 x0 = *(const float2*)(x + o0);
            float2 x1 = *(const float2*)(x + o1);
            *(float2*)(out + o0) = make_float2(acc[mt][nt][0] + x0.x, acc[mt][nt][1] + x0.y);
            *(float2*)(out + o1) = make_float2(acc[mt][nt][2] + x1.x, acc[mt][nt][3] + x1.y);
        }
}

// ---------------------------------------------------------------------------
extern "C" void kernel_launch(void* const* d_in, const int* in_sizes, int n_in,
                              void* d_out, int out_size)
{
    const float* x  = (const float*)d_in[0];
    const float* Wq = (const float*)d_in[1];
    const float* bq = (const float*)d_in[2];
    const float* Wk = (const float*)d_in[3];
    const float* bk = (const float*)d_in[4];
    const float* Wv = (const float*)d_in[5];
    const float* bv = (const float*)d_in[6];
    float* out = (float*)d_out;

    static bool attr_done = false;
    if (!attr_done) {
        cudaFuncSetAttribute(scores_kernel, cudaFuncAttributeMaxDynamicSharedMemorySize, SMEM_SC);
        cudaFuncSetAttribute(pv_kernel,     cudaFuncAttributeMaxDynamicSharedMemorySize, SMEM_PV);
        attr_done = true;
    }

    proj_kernel<<<BB * (TT / 32), 320>>>(x, Wq, bq, Wk, bk, Wv, bv);
    scores_kernel<<<dim3(TT / 128, TT / 128, BB), 256, SMEM_SC>>>();
    softmax_kernel<<<BB * TT, 256>>>();
    pv_kernel<<<dim3(TT / 128, CC / 128, BB), 256, SMEM_PV>>>(x, out);
}